// round 8
// baseline (speedup 1.0000x reference)
#include <cuda_runtime.h>

// ---------------------------------------------------------------------------
// Scratch (device globals — no dynamic allocation allowed)
// ---------------------------------------------------------------------------
__device__ float g_p0[8 * 64 * 2 * 64 * 64];   // pooled input   (n,t,2,64,64)  16 MB
__device__ float g_h1[8 * 64 * 4 * 64 * 64];   // conv1 out      (n,t,4,64,64)  33.5 MB
__device__ float g_p1[8 * 64 * 4 * 16 * 16];   // pooled spikes1 (n,t,4,16,16)   2 MB
__device__ float g_h2[8 * 64 * 8 * 16 * 16];   // conv2 out      (n,t,8,16,16)   4 MB
__device__ float g_p2[8 * 64 * 128];           // features       (n,t,128)     256 KB

// ---- f32x2 packed helpers --------------------------------------------------
__device__ __forceinline__ unsigned long long pack2(float a, float b) {
    unsigned long long r;
    asm("mov.b64 %0, {%1, %2};" : "=l"(r) : "r"(__float_as_uint(a)), "r"(__float_as_uint(b)));
    return r;
}
__device__ __forceinline__ unsigned long long fma2(unsigned long long a,
                                                   unsigned long long b,
                                                   unsigned long long c) {
    unsigned long long d;
    asm("fma.rn.f32x2 %0, %1, %2, %3;" : "=l"(d) : "l"(a), "l"(b), "l"(c));
    return d;
}
__device__ __forceinline__ float2 unpack2(unsigned long long v) {
    unsigned lo, hi;
    asm("mov.b64 {%0, %1}, %2;" : "=r"(lo), "=r"(hi) : "l"(v));
    return make_float2(__uint_as_float(lo), __uint_as_float(hi));
}

// ---------------------------------------------------------------------------
// K1: avgpool4 of inp (8,2,256,256,64) -> g_p0 (n,t,2,64,64). float4 loads
// over t (LDG.128), padded-smem transpose, coalesced writes. HBM-bound.
// ---------------------------------------------------------------------------
__global__ __launch_bounds__(256) void k_pool(const float* __restrict__ inp, int nbase) {
    int Y = blockIdx.x, c = blockIdx.y, n = nbase + blockIdx.z;
    __shared__ float sm[64 * 65];
    int tid = threadIdx.x;
    int t4 = tid & 15, Xi = tid >> 4;
    const float4* base =
        reinterpret_cast<const float4*>(inp + (((long long)(n * 2 + c) * 256 + 4 * Y) * 256) * 64) + t4;
#pragma unroll
    for (int it = 0; it < 4; ++it) {
        int X = Xi + 16 * it;
        float4 acc = make_float4(0.f, 0.f, 0.f, 0.f);
#pragma unroll
        for (int dy = 0; dy < 4; ++dy)
#pragma unroll
            for (int dx = 0; dx < 4; ++dx) {
                float4 v = base[(dy * 256 + 4 * X + dx) * 16];
                acc.x += v.x; acc.y += v.y; acc.z += v.z; acc.w += v.w;
            }
        sm[X * 65 + 4 * t4 + 0] = acc.x * 0.0625f;
        sm[X * 65 + 4 * t4 + 1] = acc.y * 0.0625f;
        sm[X * 65 + 4 * t4 + 2] = acc.z * 0.0625f;
        sm[X * 65 + 4 * t4 + 3] = acc.w * 0.0625f;
    }
    __syncthreads();
    float* ob = g_p0 + n * 524288 + c * 4096 + Y * 64;
#pragma unroll
    for (int it = 0; it < 16; ++it) {
        int idx = it * 256 + tid;
        int tw = idx >> 6, Xw = idx & 63;
        ob[tw * 8192 + Xw] = sm[Xw * 65 + tw];
    }
}

// ---------------------------------------------------------------------------
// K2: conv7 (2->4ch) on 64x64, register-blocked: thread = 4 y-rows x 4 couts
// x 2 t (f32x2). Grid per chunk: (ytile16 4, tpair 32, n 2).
// ---------------------------------------------------------------------------
__global__ __launch_bounds__(256, 2) void k_conv1mm(const float* __restrict__ w0, int nbase) {
    int tile = blockIdx.x, tp = blockIdx.y, n = nbase + blockIdx.z;
    int t0 = tp * 2;
    int tid = threadIdx.x;
    int x = tid & 63, q = tid >> 6;          // q: y-quad within 16-row tile

    __shared__ float2 si[3080];              // [cin 2][row 22][col 70], (t0,t1)
    __shared__ ulonglong2 swq[98][2];        // per tap: {(w0,w0),(w1,w1)},{(w2,w2),(w3,w3)}

    if (tid < 98) {
        int cin = tid / 49, j = tid - cin * 49;
        float wa = w0[(0 * 2 + cin) * 49 + j];
        float wb = w0[(1 * 2 + cin) * 49 + j];
        float wc = w0[(2 * 2 + cin) * 49 + j];
        float wd = w0[(3 * 2 + cin) * 49 + j];
        swq[tid][0] = make_ulonglong2(pack2(wa, wa), pack2(wb, wb));
        swq[tid][1] = make_ulonglong2(pack2(wc, wc), pack2(wd, wd));
    }

    int Y0 = tile * 16;
    const float* pt0 = g_p0 + n * 524288 + t0 * 8192;
    const float* pt1 = pt0 + 8192;
    for (int e = tid; e < 3080; e += 256) {
        int cin = e / 1540, rem = e - cin * 1540;
        int r = rem / 70, col = rem - r * 70;
        int gy = Y0 - 3 + r, gx = col - 3;
        float2 v = make_float2(0.f, 0.f);
        if ((unsigned)gy < 64u && (unsigned)gx < 64u) {
            int off = cin * 4096 + gy * 64 + gx;
            v.x = pt0[off];
            v.y = pt1[off];
        }
        si[e] = v;
    }
    __syncthreads();

    unsigned long long a[4][4];              // [row r][cout]
#pragma unroll
    for (int r = 0; r < 4; ++r)
#pragma unroll
        for (int co = 0; co < 4; ++co) a[r][co] = 0ull;

    const unsigned long long* sb = reinterpret_cast<const unsigned long long*>(si);
#pragma unroll 1
    for (int dx = 0; dx < 7; ++dx) {
#pragma unroll
        for (int cin = 0; cin < 2; ++cin) {
            const unsigned long long* colp = sb + cin * 1540 + (q * 4) * 70 + (x + dx);
            unsigned long long v[10];
#pragma unroll
            for (int r = 0; r < 10; ++r) v[r] = colp[r * 70];
#pragma unroll
            for (int dy = 0; dy < 7; ++dy) {
                ulonglong2 wA = swq[cin * 49 + dy * 7 + dx][0];
                ulonglong2 wB = swq[cin * 49 + dy * 7 + dx][1];
#pragma unroll
                for (int r = 0; r < 4; ++r) {
                    a[r][0] = fma2(v[dy + r], wA.x, a[r][0]);
                    a[r][1] = fma2(v[dy + r], wA.y, a[r][1]);
                    a[r][2] = fma2(v[dy + r], wB.x, a[r][2]);
                    a[r][3] = fma2(v[dy + r], wB.y, a[r][3]);
                }
            }
        }
    }

    long long base = ((long long)(n * 64 + t0) * 4) * 4096;
    int ybase = Y0 + q * 4;
#pragma unroll
    for (int r = 0; r < 4; ++r)
#pragma unroll
        for (int co = 0; co < 4; ++co) {
            float2 f = unpack2(a[r][co]);
            g_h1[base + co * 4096 + (ybase + r) * 64 + x]         = f.x;
            g_h1[base + 16384 + co * 4096 + (ybase + r) * 64 + x] = f.y;
        }
}

// ---------------------------------------------------------------------------
// K3: IAF scan layer 1 + fused avgpool4 -> g_p1. 2-deep prefetch.
// ---------------------------------------------------------------------------
__global__ __launch_bounds__(256) void k_iaf1(int nbase) {
    int Yp = blockIdx.x, co = blockIdx.y, n = nbase + blockIdx.z;
    int tid = threadIdx.x;
    int w = tid >> 5, lane = tid & 31;
    int yin = lane >> 3, x8 = lane & 7;
    int x = w * 8 + x8;
    int y = Yp * 4 + yin;

    const float* hb = g_h1 + (long long)(n * 64) * 16384 + co * 4096 + y * 64 + x;
    float* ob = g_p1 + (n * 64) * 1024 + co * 256 + Yp * 16 + (x >> 2);
    const unsigned m = 0xffffffffu;

    float v = 0.f;
    float n0 = hb[0];
    float n1 = hb[16384];
    for (int t = 0; t < 64; ++t) {
        float hv = n0;
        n0 = n1;
        if (t < 62) n1 = hb[(t + 2) * 16384];
        v += hv;
        float sp = (v >= 1.f) ? 1.f : 0.f;
        v -= sp;
        sp += __shfl_down_sync(m, sp, 1);
        sp += __shfl_down_sync(m, sp, 2);
        sp += __shfl_down_sync(m, sp, 8);
        sp += __shfl_down_sync(m, sp, 16);
        if (yin == 0 && (x8 & 3) == 0) ob[t * 1024] = sp * 0.0625f;
    }
}

// ---------------------------------------------------------------------------
// K4: conv7 (4->8ch) on 16x16, t-pair packed f32x2: thread = 2 y-rows x
// 4 couts x 2 t. Grid per chunk: (tp 32, n 2), 256 threads.
// ---------------------------------------------------------------------------
__global__ __launch_bounds__(256) void k_conv2mm(const float* __restrict__ w1, int nbase) {
    int tp = blockIdx.x, n = nbase + blockIdx.y;
    int t0 = tp * 2;
    int tid = threadIdx.x;
    int h = tid >> 7;                        // cout half (couts h*4..h*4+3)
    int lt = tid & 127;
    int x = lt & 15, q8 = lt >> 4;           // rows 2*q8, 2*q8+1

    __shared__ float2 si[1936];              // [cin 4][22][22], (t0,t1)
    __shared__ ulonglong2 swq[2][196][2];    // [half][tap]: 4 couts as (w,w) pairs

    for (int e = tid; e < 392; e += 256) {
        int hh = e / 196, j = e - hh * 196;
        int cin = j / 49, k = j - cin * 49;
        float wa = w1[((hh * 4 + 0) * 4 + cin) * 49 + k];
        float wb = w1[((hh * 4 + 1) * 4 + cin) * 49 + k];
        float wc = w1[((hh * 4 + 2) * 4 + cin) * 49 + k];
        float wd = w1[((hh * 4 + 3) * 4 + cin) * 49 + k];
        swq[hh][j][0] = make_ulonglong2(pack2(wa, wa), pack2(wb, wb));
        swq[hh][j][1] = make_ulonglong2(pack2(wc, wc), pack2(wd, wd));
    }

    const float* pt0 = g_p1 + n * 65536 + t0 * 1024;
    const float* pt1 = pt0 + 1024;
    for (int e = tid; e < 1936; e += 256) {
        int cin = e / 484, rem = e - cin * 484;
        int r = rem / 22, col = rem - r * 22;
        int gy = r - 3, gx = col - 3;
        float2 v = make_float2(0.f, 0.f);
        if ((unsigned)gy < 16u && (unsigned)gx < 16u) {
            int off = cin * 256 + gy * 16 + gx;
            v.x = pt0[off];
            v.y = pt1[off];
        }
        si[e] = v;
    }
    __syncthreads();

    unsigned long long a[2][4];              // [row r][cout within half]
#pragma unroll
    for (int r = 0; r < 2; ++r)
#pragma unroll
        for (int co = 0; co < 4; ++co) a[r][co] = 0ull;

    const unsigned long long* sb = reinterpret_cast<const unsigned long long*>(si);
#pragma unroll 1
    for (int dx = 0; dx < 7; ++dx) {
#pragma unroll
        for (int cin = 0; cin < 4; ++cin) {
            const unsigned long long* colp = sb + cin * 484 + (q8 * 2) * 22 + (x + dx);
            unsigned long long v[8];
#pragma unroll
            for (int r = 0; r < 8; ++r) v[r] = colp[r * 22];
#pragma unroll
            for (int dy = 0; dy < 7; ++dy) {
                ulonglong2 wA = swq[h][cin * 49 + dy * 7 + dx][0];
                ulonglong2 wB = swq[h][cin * 49 + dy * 7 + dx][1];
                a[0][0] = fma2(v[dy],     wA.x, a[0][0]);
                a[0][1] = fma2(v[dy],     wA.y, a[0][1]);
                a[0][2] = fma2(v[dy],     wB.x, a[0][2]);
                a[0][3] = fma2(v[dy],     wB.y, a[0][3]);
                a[1][0] = fma2(v[dy + 1], wA.x, a[1][0]);
                a[1][1] = fma2(v[dy + 1], wA.y, a[1][1]);
                a[1][2] = fma2(v[dy + 1], wB.x, a[1][2]);
                a[1][3] = fma2(v[dy + 1], wB.y, a[1][3]);
            }
        }
    }

    float* hb = g_h2 + (long long)(n * 64 + t0) * 2048;
#pragma unroll
    for (int r = 0; r < 2; ++r) {
        int yo = (q8 * 2 + r) * 16 + x;
#pragma unroll
        for (int co = 0; co < 4; ++co) {
            float2 f = unpack2(a[r][co]);
            hb[(h * 4 + co) * 256 + yo]        = f.x;   // t0
            hb[2048 + (h * 4 + co) * 256 + yo] = f.y;   // t0+1
        }
    }
}

// ---------------------------------------------------------------------------
// K5: IAF scan layer 2 + avgpool4 -> g_p2 (n,t,128). 2-deep prefetch.
// ---------------------------------------------------------------------------
__global__ __launch_bounds__(256) void k_iaf2(int nbase) {
    int co = blockIdx.x, n = nbase + blockIdx.y;
    int tid = threadIdx.x;
    int w = tid >> 5, lane = tid & 31;
    int yin = lane >> 3, x8 = lane & 7;
    int y = (w >> 1) * 4 + yin;
    int x = (w & 1) * 8 + x8;
    int g = (y >> 2) * 4 + (x >> 2);

    const float* hb = g_h2 + (long long)(n * 64) * 2048 + co * 256 + y * 16 + x;
    float* ob = g_p2 + (n * 64) * 128 + co * 16 + g;
    const unsigned m = 0xffffffffu;

    float v = 0.f;
    float n0 = hb[0];
    float n1 = hb[2048];
    for (int t = 0; t < 64; ++t) {
        float hv = n0;
        n0 = n1;
        if (t < 62) n1 = hb[(t + 2) * 2048];
        v += hv;
        float sp = (v >= 1.f) ? 1.f : 0.f;
        v -= sp;
        sp += __shfl_down_sync(m, sp, 1);
        sp += __shfl_down_sync(m, sp, 2);
        sp += __shfl_down_sync(m, sp, 8);
        sp += __shfl_down_sync(m, sp, 16);
        if (yin == 0 && (x8 & 3) == 0) ob[t * 128] = sp * 0.0625f;
    }
}

// ---------------------------------------------------------------------------
// K6: out[n][cls][t] = sum_f feat[n][t][f] * wl[cls][f]. Grid 128 per chunk.
// ---------------------------------------------------------------------------
__global__ __launch_bounds__(128) void k_fc(const float* __restrict__ wl,
                                            float* __restrict__ out, int nbase) {
    int b = blockIdx.x;                      // (n-nbase)*64 + t
    int tid = threadIdx.x;
    int n = nbase + (b >> 6), t = b & 63;
    float v = g_p2[(n * 64 + t) * 128 + tid];
    float c0 = v * wl[tid];
    float c1 = v * wl[128 + tid];
    const unsigned m = 0xffffffffu;
#pragma unroll
    for (int o = 16; o; o >>= 1) {
        c0 += __shfl_down_sync(m, c0, o);
        c1 += __shfl_down_sync(m, c1, o);
    }
    __shared__ float r0[4], r1[4];
    if ((tid & 31) == 0) { r0[tid >> 5] = c0; r1[tid >> 5] = c1; }
    __syncthreads();
    if (tid == 0) {
        out[n * 128 + t]      = (r0[0] + r0[1]) + (r0[2] + r0[3]);
        out[n * 128 + 64 + t] = (r1[0] + r1[1]) + (r1[2] + r1[3]);
    }
}

// ---------------------------------------------------------------------------
// Launch: 4 n-chunks pipelined over 2 worker streams. Pools run back-to-back
// on the (captured) default stream; each chunk's conv chain forks off via an
// event after its pool and joins at the end. Streams/events are created once
// on the first (uncaptured correctness) call and reused — device work per
// call is identical. Fallback: sequential on the default stream.
// ---------------------------------------------------------------------------
extern "C" void kernel_launch(void* const* d_in, const int* in_sizes, int n_in,
                              void* d_out, int out_size) {
    const float *inp = nullptr, *w0 = nullptr, *w1 = nullptr, *wl = nullptr;
    for (int i = 0; i < n_in; ++i) {
        switch (in_sizes[i]) {
            case 67108864: inp = (const float*)d_in[i]; break;  // (8,2,256,256,64)
            case 392:      w0  = (const float*)d_in[i]; break;  // (4,2,7,7)
            case 1568:     w1  = (const float*)d_in[i]; break;  // (8,4,7,7)
            case 256:      wl  = (const float*)d_in[i]; break;  // (2,128)
        }
    }
    if (!inp) inp = (const float*)d_in[0];
    if (!w0)  w0  = (const float*)d_in[1];
    if (!w1)  w1  = (const float*)d_in[2];
    if (!wl)  wl  = (const float*)d_in[3];
    float* out = (float*)d_out;

    static cudaStream_t ws[2] = {nullptr, nullptr};
    static cudaEvent_t evp[4], evf[4];
    static int init_state = 0;               // 0=untried, 1=ok, -1=failed
    if (init_state == 0) {
        bool ok = (cudaStreamCreateWithFlags(&ws[0], cudaStreamNonBlocking) == cudaSuccess) &&
                  (cudaStreamCreateWithFlags(&ws[1], cudaStreamNonBlocking) == cudaSuccess);
        for (int i = 0; i < 4 && ok; ++i)
            ok = (cudaEventCreateWithFlags(&evp[i], cudaEventDisableTiming) == cudaSuccess) &&
                 (cudaEventCreateWithFlags(&evf[i], cudaEventDisableTiming) == cudaSuccess);
        init_state = ok ? 1 : -1;
    }

    if (init_state == 1) {
        // Pools back-to-back on the default (captured) stream, event per chunk.
        for (int c = 0; c < 4; ++c) {
            k_pool<<<dim3(64, 2, 2), 256>>>(inp, 2 * c);
            cudaEventRecord(evp[c], 0);
        }
        // Conv chains forked onto worker streams.
        for (int c = 0; c < 4; ++c) {
            cudaStream_t s = ws[c & 1];
            cudaStreamWaitEvent(s, evp[c], 0);
            k_conv1mm<<<dim3(4, 32, 2), 256, 0, s>>>(w0, 2 * c);
            k_iaf1   <<<dim3(16, 4, 2), 256, 0, s>>>(2 * c);
            k_conv2mm<<<dim3(32, 2),    256, 0, s>>>(w1, 2 * c);
            k_iaf2   <<<dim3(8, 2),     256, 0, s>>>(2 * c);
            k_fc     <<<128,            128, 0, s>>>(wl, out, 2 * c);
            cudaEventRecord(evf[c], s);
        }
        // Join everything back into the default stream.
        for (int c = 0; c < 4; ++c) cudaStreamWaitEvent(0, evf[c], 0);
    } else {
        // Fallback: fully sequential on the default stream.
        for (int c = 0; c < 4; ++c) k_pool<<<dim3(64, 2, 2), 256>>>(inp, 2 * c);
        for (int c = 0; c < 4; ++c) {
            k_conv1mm<<<dim3(4, 32, 2), 256>>>(w0, 2 * c);
            k_iaf1   <<<dim3(16, 4, 2), 256>>>(2 * c);
            k_conv2mm<<<dim3(32, 2),    256>>>(w1, 2 * c);
            k_iaf2   <<<dim3(8, 2),     256>>>(2 * c);
            k_fc     <<<128,            128>>>(wl, out, 2 * c);
        }
    }
}

// round 9
// speedup vs baseline: 1.1687x; 1.1687x over previous
#include <cuda_runtime.h>

// ---------------------------------------------------------------------------
// Scratch (device globals — no dynamic allocation allowed)
// ---------------------------------------------------------------------------
__device__ float g_p0[8 * 64 * 2 * 64 * 64];   // pooled input   (n,t,2,64,64)  16 MB
__device__ float g_h1[8 * 64 * 4 * 64 * 64];   // conv1 out      (n,t,4,64,64)  33.5 MB
__device__ float g_p1[8 * 64 * 4 * 16 * 16];   // pooled spikes1 (n,t,4,16,16)   2 MB
__device__ float g_h2[8 * 64 * 8 * 16 * 16];   // conv2 out      (n,t,8,16,16)   4 MB
__device__ float g_p2[8 * 64 * 128];           // features       (n,t,128)     256 KB

// ---- f32x2 packed helpers --------------------------------------------------
__device__ __forceinline__ unsigned long long pack2(float a, float b) {
    unsigned long long r;
    asm("mov.b64 %0, {%1, %2};" : "=l"(r) : "r"(__float_as_uint(a)), "r"(__float_as_uint(b)));
    return r;
}
__device__ __forceinline__ unsigned long long fma2(unsigned long long a,
                                                   unsigned long long b,
                                                   unsigned long long c) {
    unsigned long long d;
    asm("fma.rn.f32x2 %0, %1, %2, %3;" : "=l"(d) : "l"(a), "l"(b), "l"(c));
    return d;
}
__device__ __forceinline__ float2 unpack2(unsigned long long v) {
    unsigned lo, hi;
    asm("mov.b64 {%0, %1}, %2;" : "=r"(lo), "=r"(hi) : "l"(v));
    return make_float2(__uint_as_float(lo), __uint_as_float(hi));
}

// ---------------------------------------------------------------------------
// K1: avgpool4 of inp (8,2,256,256,64) -> g_p0 (n,t,2,64,64). float4 loads
// over t (LDG.128), padded-smem transpose, coalesced writes. HBM-bound.
// ---------------------------------------------------------------------------
__global__ __launch_bounds__(256) void k_pool(const float* __restrict__ inp) {
    int Y = blockIdx.x, c = blockIdx.y, n = blockIdx.z;
    __shared__ float sm[64 * 65];
    int tid = threadIdx.x;
    int t4 = tid & 15, Xi = tid >> 4;
    const float4* base =
        reinterpret_cast<const float4*>(inp + (((long long)(n * 2 + c) * 256 + 4 * Y) * 256) * 64) + t4;
#pragma unroll
    for (int it = 0; it < 4; ++it) {
        int X = Xi + 16 * it;
        float4 acc = make_float4(0.f, 0.f, 0.f, 0.f);
#pragma unroll
        for (int dy = 0; dy < 4; ++dy)
#pragma unroll
            for (int dx = 0; dx < 4; ++dx) {
                float4 v = base[(dy * 256 + 4 * X + dx) * 16];
                acc.x += v.x; acc.y += v.y; acc.z += v.z; acc.w += v.w;
            }
        sm[X * 65 + 4 * t4 + 0] = acc.x * 0.0625f;
        sm[X * 65 + 4 * t4 + 1] = acc.y * 0.0625f;
        sm[X * 65 + 4 * t4 + 2] = acc.z * 0.0625f;
        sm[X * 65 + 4 * t4 + 3] = acc.w * 0.0625f;
    }
    __syncthreads();
    float* ob = g_p0 + n * 524288 + c * 4096 + Y * 64;
#pragma unroll
    for (int it = 0; it < 16; ++it) {
        int idx = it * 256 + tid;
        int tw = idx >> 6, Xw = idx & 63;
        ob[tw * 8192 + Xw] = sm[Xw * 65 + tw];
    }
}

// ---------------------------------------------------------------------------
// K2: conv7 (2->4ch) on 64x64, 8-row tiles for occupancy: thread = 2 y-rows
// x 4 couts x 2 t (f32x2). Grid (ytile8 8, tp 32, n 8) = 2048 blocks x 256.
// Per (dx,cin): 8 LDS.64 feed 56 FMA2.
// ---------------------------------------------------------------------------
__global__ __launch_bounds__(256) void k_conv1mm(const float* __restrict__ w0) {
    int tile = blockIdx.x, tp = blockIdx.y, n = blockIdx.z;
    int t0 = tp * 2;
    int tid = threadIdx.x;
    int x = tid & 63, q = tid >> 6;          // q: row-pair (rows 2q, 2q+1 of 8)

    __shared__ float2 si[1960];              // [cin 2][row 14][col 70], (t0,t1)
    __shared__ ulonglong2 swq[98][2];        // per tap: {(w0,w0),(w1,w1)},{(w2,w2),(w3,w3)}

    if (tid < 98) {
        int cin = tid / 49, j = tid - cin * 49;
        float wa = w0[(0 * 2 + cin) * 49 + j];
        float wb = w0[(1 * 2 + cin) * 49 + j];
        float wc = w0[(2 * 2 + cin) * 49 + j];
        float wd = w0[(3 * 2 + cin) * 49 + j];
        swq[tid][0] = make_ulonglong2(pack2(wa, wa), pack2(wb, wb));
        swq[tid][1] = make_ulonglong2(pack2(wc, wc), pack2(wd, wd));
    }

    int Y0 = tile * 8;
    const float* pt0 = g_p0 + n * 524288 + t0 * 8192;
    const float* pt1 = pt0 + 8192;
    for (int e = tid; e < 1960; e += 256) {
        int cin = e / 980, rem = e - cin * 980;
        int r = rem / 70, col = rem - r * 70;
        int gy = Y0 - 3 + r, gx = col - 3;
        float2 v = make_float2(0.f, 0.f);
        if ((unsigned)gy < 64u && (unsigned)gx < 64u) {
            int off = cin * 4096 + gy * 64 + gx;
            v.x = pt0[off];
            v.y = pt1[off];
        }
        si[e] = v;
    }
    __syncthreads();

    unsigned long long a[2][4];              // [row r][cout]
#pragma unroll
    for (int r = 0; r < 2; ++r)
#pragma unroll
        for (int co = 0; co < 4; ++co) a[r][co] = 0ull;

    const unsigned long long* sb = reinterpret_cast<const unsigned long long*>(si);
#pragma unroll 1
    for (int dx = 0; dx < 7; ++dx) {
#pragma unroll
        for (int cin = 0; cin < 2; ++cin) {
            const unsigned long long* colp = sb + cin * 980 + (q * 2) * 70 + (x + dx);
            unsigned long long v[8];
#pragma unroll
            for (int r = 0; r < 8; ++r) v[r] = colp[r * 70];
#pragma unroll
            for (int dy = 0; dy < 7; ++dy) {
                ulonglong2 wA = swq[cin * 49 + dy * 7 + dx][0];
                ulonglong2 wB = swq[cin * 49 + dy * 7 + dx][1];
                a[0][0] = fma2(v[dy],     wA.x, a[0][0]);
                a[0][1] = fma2(v[dy],     wA.y, a[0][1]);
                a[0][2] = fma2(v[dy],     wB.x, a[0][2]);
                a[0][3] = fma2(v[dy],     wB.y, a[0][3]);
                a[1][0] = fma2(v[dy + 1], wA.x, a[1][0]);
                a[1][1] = fma2(v[dy + 1], wA.y, a[1][1]);
                a[1][2] = fma2(v[dy + 1], wB.x, a[1][2]);
                a[1][3] = fma2(v[dy + 1], wB.y, a[1][3]);
            }
        }
    }

    long long base = ((long long)(n * 64 + t0) * 4) * 4096;
    int ybase = Y0 + q * 2;
#pragma unroll
    for (int r = 0; r < 2; ++r)
#pragma unroll
        for (int co = 0; co < 4; ++co) {
            float2 f = unpack2(a[r][co]);
            g_h1[base + co * 4096 + (ybase + r) * 64 + x]         = f.x;
            g_h1[base + 16384 + co * 4096 + (ybase + r) * 64 + x] = f.y;
        }
}

// ---------------------------------------------------------------------------
// K3: IAF scan layer 1 + fused avgpool4 -> g_p1. 2-deep prefetch.
// ---------------------------------------------------------------------------
__global__ __launch_bounds__(256) void k_iaf1() {
    int Yp = blockIdx.x, co = blockIdx.y, n = blockIdx.z;
    int tid = threadIdx.x;
    int w = tid >> 5, lane = tid & 31;
    int yin = lane >> 3, x8 = lane & 7;
    int x = w * 8 + x8;
    int y = Yp * 4 + yin;

    const float* hb = g_h1 + (long long)(n * 64) * 16384 + co * 4096 + y * 64 + x;
    float* ob = g_p1 + (n * 64) * 1024 + co * 256 + Yp * 16 + (x >> 2);
    const unsigned m = 0xffffffffu;

    float v = 0.f;
    float n0 = hb[0];
    float n1 = hb[16384];
    for (int t = 0; t < 64; ++t) {
        float hv = n0;
        n0 = n1;
        if (t < 62) n1 = hb[(t + 2) * 16384];
        v += hv;
        float sp = (v >= 1.f) ? 1.f : 0.f;
        v -= sp;
        sp += __shfl_down_sync(m, sp, 1);
        sp += __shfl_down_sync(m, sp, 2);
        sp += __shfl_down_sync(m, sp, 8);
        sp += __shfl_down_sync(m, sp, 16);
        if (yin == 0 && (x8 & 3) == 0) ob[t * 1024] = sp * 0.0625f;
    }
}

// ---------------------------------------------------------------------------
// K4: conv7 (4->8ch) on 16x16, 4-row tiles + cout-halves for occupancy:
// thread = 1 row x 4 couts x 2 t (f32x2). Grid (ytile4 4, tp 32, n 8) =
// 1024 blocks x 128 threads (16x x 4r x 2 halves) = 4096 warps.
// Per (cin,dx): 7 LDS.64 feed 28 FMA2.
// ---------------------------------------------------------------------------
__global__ __launch_bounds__(128) void k_conv2mm(const float* __restrict__ w1) {
    int tile = blockIdx.x, tp = blockIdx.y, n = blockIdx.z;
    int t0 = tp * 2;
    int tid = threadIdx.x;
    int x = tid & 15, r0 = (tid >> 4) & 3, h = tid >> 6;   // row Y0+r0, couts h*4..h*4+3

    __shared__ float2 si[880];               // [cin 4][row 10][col 22], (t0,t1)
    __shared__ ulonglong2 swq[2][196][2];    // [half][tap]: 4 couts as (w,w) pairs

    for (int e = tid; e < 392; e += 128) {
        int hh = e / 196, j = e - hh * 196;
        int cin = j / 49, k = j - cin * 49;
        float wa = w1[((hh * 4 + 0) * 4 + cin) * 49 + k];
        float wb = w1[((hh * 4 + 1) * 4 + cin) * 49 + k];
        float wc = w1[((hh * 4 + 2) * 4 + cin) * 49 + k];
        float wd = w1[((hh * 4 + 3) * 4 + cin) * 49 + k];
        swq[hh][j][0] = make_ulonglong2(pack2(wa, wa), pack2(wb, wb));
        swq[hh][j][1] = make_ulonglong2(pack2(wc, wc), pack2(wd, wd));
    }

    int Y0 = tile * 4;
    const float* pt0 = g_p1 + n * 65536 + t0 * 1024;
    const float* pt1 = pt0 + 1024;
    for (int e = tid; e < 880; e += 128) {
        int cin = e / 220, rem = e - cin * 220;
        int rr = rem / 22, col = rem - rr * 22;
        int gy = Y0 - 3 + rr, gx = col - 3;
        float2 v = make_float2(0.f, 0.f);
        if ((unsigned)gy < 16u && (unsigned)gx < 16u) {
            int off = cin * 256 + gy * 16 + gx;
            v.x = pt0[off];
            v.y = pt1[off];
        }
        si[e] = v;
    }
    __syncthreads();

    unsigned long long a[4];                 // couts h*4..h*4+3
#pragma unroll
    for (int co = 0; co < 4; ++co) a[co] = 0ull;

    const unsigned long long* sb = reinterpret_cast<const unsigned long long*>(si);
#pragma unroll 1
    for (int dx = 0; dx < 7; ++dx) {
#pragma unroll
        for (int cin = 0; cin < 4; ++cin) {
            const unsigned long long* colp = sb + cin * 220 + r0 * 22 + (x + dx);
            unsigned long long v[7];
#pragma unroll
            for (int j = 0; j < 7; ++j) v[j] = colp[j * 22];
#pragma unroll
            for (int dy = 0; dy < 7; ++dy) {
                ulonglong2 wA = swq[h][cin * 49 + dy * 7 + dx][0];
                ulonglong2 wB = swq[h][cin * 49 + dy * 7 + dx][1];
                a[0] = fma2(v[dy], wA.x, a[0]);
                a[1] = fma2(v[dy], wA.y, a[1]);
                a[2] = fma2(v[dy], wB.x, a[2]);
                a[3] = fma2(v[dy], wB.y, a[3]);
            }
        }
    }

    float* hb = g_h2 + (long long)(n * 64 + t0) * 2048;
    int yo = (Y0 + r0) * 16 + x;
#pragma unroll
    for (int co = 0; co < 4; ++co) {
        float2 f = unpack2(a[co]);
        hb[(h * 4 + co) * 256 + yo]        = f.x;   // t0
        hb[2048 + (h * 4 + co) * 256 + yo] = f.y;   // t0+1
    }
}

// ---------------------------------------------------------------------------
// K5: IAF scan layer 2 + avgpool4 -> g_p2 (n,t,128). 2-deep prefetch.
// ---------------------------------------------------------------------------
__global__ __launch_bounds__(256) void k_iaf2() {
    int co = blockIdx.x, n = blockIdx.y;
    int tid = threadIdx.x;
    int w = tid >> 5, lane = tid & 31;
    int yin = lane >> 3, x8 = lane & 7;
    int y = (w >> 1) * 4 + yin;
    int x = (w & 1) * 8 + x8;
    int g = (y >> 2) * 4 + (x >> 2);

    const float* hb = g_h2 + (long long)(n * 64) * 2048 + co * 256 + y * 16 + x;
    float* ob = g_p2 + (n * 64) * 128 + co * 16 + g;
    const unsigned m = 0xffffffffu;

    float v = 0.f;
    float n0 = hb[0];
    float n1 = hb[2048];
    for (int t = 0; t < 64; ++t) {
        float hv = n0;
        n0 = n1;
        if (t < 62) n1 = hb[(t + 2) * 2048];
        v += hv;
        float sp = (v >= 1.f) ? 1.f : 0.f;
        v -= sp;
        sp += __shfl_down_sync(m, sp, 1);
        sp += __shfl_down_sync(m, sp, 2);
        sp += __shfl_down_sync(m, sp, 8);
        sp += __shfl_down_sync(m, sp, 16);
        if (yin == 0 && (x8 & 3) == 0) ob[t * 128] = sp * 0.0625f;
    }
}

// ---------------------------------------------------------------------------
// K6: out[n][cls][t] = sum_f feat[n][t][f] * wl[cls][f]   -> (8,2,64)
// ---------------------------------------------------------------------------
__global__ __launch_bounds__(128) void k_fc(const float* __restrict__ wl,
                                            float* __restrict__ out) {
    int b = blockIdx.x;          // n*64 + t
    int tid = threadIdx.x;
    float v = g_p2[b * 128 + tid];
    float c0 = v * wl[tid];
    float c1 = v * wl[128 + tid];
    const unsigned m = 0xffffffffu;
#pragma unroll
    for (int o = 16; o; o >>= 1) {
        c0 += __shfl_down_sync(m, c0, o);
        c1 += __shfl_down_sync(m, c1, o);
    }
    __shared__ float r0[4], r1[4];
    if ((tid & 31) == 0) { r0[tid >> 5] = c0; r1[tid >> 5] = c1; }
    __syncthreads();
    if (tid == 0) {
        int n = b >> 6, t = b & 63;
        out[n * 128 + t]      = (r0[0] + r0[1]) + (r0[2] + r0[3]);
        out[n * 128 + 64 + t] = (r1[0] + r1[1]) + (r1[2] + r1[3]);
    }
}

// ---------------------------------------------------------------------------
extern "C" void kernel_launch(void* const* d_in, const int* in_sizes, int n_in,
                              void* d_out, int out_size) {
    const float *inp = nullptr, *w0 = nullptr, *w1 = nullptr, *wl = nullptr;
    for (int i = 0; i < n_in; ++i) {
        switch (in_sizes[i]) {
            case 67108864: inp = (const float*)d_in[i]; break;  // (8,2,256,256,64)
            case 392:      w0  = (const float*)d_in[i]; break;  // (4,2,7,7)
            case 1568:     w1  = (const float*)d_in[i]; break;  // (8,4,7,7)
            case 256:      wl  = (const float*)d_in[i]; break;  // (2,128)
        }
    }
    if (!inp) inp = (const float*)d_in[0];
    if (!w0)  w0  = (const float*)d_in[1];
    if (!w1)  w1  = (const float*)d_in[2];
    if (!wl)  wl  = (const float*)d_in[3];

    k_pool   <<<dim3(64, 2, 8),  256>>>(inp);
    k_conv1mm<<<dim3(8, 32, 8),  256>>>(w0);
    k_iaf1   <<<dim3(16, 4, 8),  256>>>();
    k_conv2mm<<<dim3(4, 32, 8),  128>>>(w1);
    k_iaf2   <<<dim3(8, 8),      256>>>();
    k_fc     <<<512,             128>>>(wl, (float*)d_out);
}

// round 10
// speedup vs baseline: 1.2178x; 1.0421x over previous
#include <cuda_runtime.h>

// ---------------------------------------------------------------------------
// Scratch (device globals — no dynamic allocation allowed)
// ---------------------------------------------------------------------------
__device__ float g_p0[8 * 64 * 2 * 64 * 64];   // pooled input   (n,t,2,64,64)  16 MB
__device__ float g_h1[8 * 64 * 4 * 64 * 64];   // conv1 out      (n,t,4,64,64)  33.5 MB
__device__ float g_p1[8 * 64 * 4 * 16 * 16];   // pooled spikes1 (n,t,4,16,16)   2 MB
__device__ float g_h2[8 * 64 * 8 * 16 * 16];   // conv2 out      (n,t,8,16,16)   4 MB
__device__ float g_p2[8 * 64 * 128];           // features       (n,t,128)     256 KB

// ---- f32x2 packed helpers --------------------------------------------------
__device__ __forceinline__ unsigned long long pack2(float a, float b) {
    unsigned long long r;
    asm("mov.b64 %0, {%1, %2};" : "=l"(r) : "r"(__float_as_uint(a)), "r"(__float_as_uint(b)));
    return r;
}
__device__ __forceinline__ unsigned long long fma2(unsigned long long a,
                                                   unsigned long long b,
                                                   unsigned long long c) {
    unsigned long long d;
    asm("fma.rn.f32x2 %0, %1, %2, %3;" : "=l"(d) : "l"(a), "l"(b), "l"(c));
    return d;
}
__device__ __forceinline__ float2 unpack2(unsigned long long v) {
    unsigned lo, hi;
    asm("mov.b64 {%0, %1}, %2;" : "=r"(lo), "=r"(hi) : "l"(v));
    return make_float2(__uint_as_float(lo), __uint_as_float(hi));
}

// ---------------------------------------------------------------------------
// K1: avgpool4 of inp (8,2,256,256,64) -> g_p0 (n,t,2,64,64). float4 loads
// over t (LDG.128), padded-smem transpose, coalesced writes. HBM-bound.
// ---------------------------------------------------------------------------
__global__ __launch_bounds__(256) void k_pool(const float* __restrict__ inp) {
    int Y = blockIdx.x, c = blockIdx.y, n = blockIdx.z;
    __shared__ float sm[64 * 65];
    int tid = threadIdx.x;
    int t4 = tid & 15, Xi = tid >> 4;
    const float4* base =
        reinterpret_cast<const float4*>(inp + (((long long)(n * 2 + c) * 256 + 4 * Y) * 256) * 64) + t4;
#pragma unroll
    for (int it = 0; it < 4; ++it) {
        int X = Xi + 16 * it;
        float4 acc = make_float4(0.f, 0.f, 0.f, 0.f);
#pragma unroll
        for (int dy = 0; dy < 4; ++dy)
#pragma unroll
            for (int dx = 0; dx < 4; ++dx) {
                float4 v = base[(dy * 256 + 4 * X + dx) * 16];
                acc.x += v.x; acc.y += v.y; acc.z += v.z; acc.w += v.w;
            }
        sm[X * 65 + 4 * t4 + 0] = acc.x * 0.0625f;
        sm[X * 65 + 4 * t4 + 1] = acc.y * 0.0625f;
        sm[X * 65 + 4 * t4 + 2] = acc.z * 0.0625f;
        sm[X * 65 + 4 * t4 + 3] = acc.w * 0.0625f;
    }
    __syncthreads();
    float* ob = g_p0 + n * 524288 + c * 4096 + Y * 64;
#pragma unroll
    for (int it = 0; it < 16; ++it) {
        int idx = it * 256 + tid;
        int tw = idx >> 6, Xw = idx & 63;
        ob[tw * 8192 + Xw] = sm[Xw * 65 + tw];
    }
}

// ---------------------------------------------------------------------------
// K2: conv7 (2->4ch) on 64x64, 8-row tiles (R9 winner): thread = 2 y-rows
// x 4 couts x 2 t (f32x2). Grid (ytile8 8, tp 32, n 8) = 2048 blocks x 256.
// Per (dx,cin): 8 LDS.64 feed 56 FMA2.
// ---------------------------------------------------------------------------
__global__ __launch_bounds__(256) void k_conv1mm(const float* __restrict__ w0) {
    int tile = blockIdx.x, tp = blockIdx.y, n = blockIdx.z;
    int t0 = tp * 2;
    int tid = threadIdx.x;
    int x = tid & 63, q = tid >> 6;          // q: row-pair (rows 2q, 2q+1 of 8)

    __shared__ float2 si[1960];              // [cin 2][row 14][col 70], (t0,t1)
    __shared__ ulonglong2 swq[98][2];        // per tap: {(w0,w0),(w1,w1)},{(w2,w2),(w3,w3)}

    if (tid < 98) {
        int cin = tid / 49, j = tid - cin * 49;
        float wa = w0[(0 * 2 + cin) * 49 + j];
        float wb = w0[(1 * 2 + cin) * 49 + j];
        float wc = w0[(2 * 2 + cin) * 49 + j];
        float wd = w0[(3 * 2 + cin) * 49 + j];
        swq[tid][0] = make_ulonglong2(pack2(wa, wa), pack2(wb, wb));
        swq[tid][1] = make_ulonglong2(pack2(wc, wc), pack2(wd, wd));
    }

    int Y0 = tile * 8;
    const float* pt0 = g_p0 + n * 524288 + t0 * 8192;
    const float* pt1 = pt0 + 8192;
    for (int e = tid; e < 1960; e += 256) {
        int cin = e / 980, rem = e - cin * 980;
        int r = rem / 70, col = rem - r * 70;
        int gy = Y0 - 3 + r, gx = col - 3;
        float2 v = make_float2(0.f, 0.f);
        if ((unsigned)gy < 64u && (unsigned)gx < 64u) {
            int off = cin * 4096 + gy * 64 + gx;
            v.x = pt0[off];
            v.y = pt1[off];
        }
        si[e] = v;
    }
    __syncthreads();

    unsigned long long a[2][4];              // [row r][cout]
#pragma unroll
    for (int r = 0; r < 2; ++r)
#pragma unroll
        for (int co = 0; co < 4; ++co) a[r][co] = 0ull;

    const unsigned long long* sb = reinterpret_cast<const unsigned long long*>(si);
#pragma unroll 1
    for (int dx = 0; dx < 7; ++dx) {
#pragma unroll
        for (int cin = 0; cin < 2; ++cin) {
            const unsigned long long* colp = sb + cin * 980 + (q * 2) * 70 + (x + dx);
            unsigned long long v[8];
#pragma unroll
            for (int r = 0; r < 8; ++r) v[r] = colp[r * 70];
#pragma unroll
            for (int dy = 0; dy < 7; ++dy) {
                ulonglong2 wA = swq[cin * 49 + dy * 7 + dx][0];
                ulonglong2 wB = swq[cin * 49 + dy * 7 + dx][1];
                a[0][0] = fma2(v[dy],     wA.x, a[0][0]);
                a[0][1] = fma2(v[dy],     wA.y, a[0][1]);
                a[0][2] = fma2(v[dy],     wB.x, a[0][2]);
                a[0][3] = fma2(v[dy],     wB.y, a[0][3]);
                a[1][0] = fma2(v[dy + 1], wA.x, a[1][0]);
                a[1][1] = fma2(v[dy + 1], wA.y, a[1][1]);
                a[1][2] = fma2(v[dy + 1], wB.x, a[1][2]);
                a[1][3] = fma2(v[dy + 1], wB.y, a[1][3]);
            }
        }
    }

    long long base = ((long long)(n * 64 + t0) * 4) * 4096;
    int ybase = Y0 + q * 2;
#pragma unroll
    for (int r = 0; r < 2; ++r)
#pragma unroll
        for (int co = 0; co < 4; ++co) {
            float2 f = unpack2(a[r][co]);
            g_h1[base + co * 4096 + (ybase + r) * 64 + x]         = f.x;
            g_h1[base + 16384 + co * 4096 + (ybase + r) * 64 + x] = f.y;
        }
}

// ---------------------------------------------------------------------------
// K3: IAF scan layer 1 + fused avgpool4 -> g_p1. 2-deep prefetch.
// ---------------------------------------------------------------------------
__global__ __launch_bounds__(256) void k_iaf1() {
    int Yp = blockIdx.x, co = blockIdx.y, n = blockIdx.z;
    int tid = threadIdx.x;
    int w = tid >> 5, lane = tid & 31;
    int yin = lane >> 3, x8 = lane & 7;
    int x = w * 8 + x8;
    int y = Yp * 4 + yin;

    const float* hb = g_h1 + (long long)(n * 64) * 16384 + co * 4096 + y * 64 + x;
    float* ob = g_p1 + (n * 64) * 1024 + co * 256 + Yp * 16 + (x >> 2);
    const unsigned m = 0xffffffffu;

    float v = 0.f;
    float n0 = hb[0];
    float n1 = hb[16384];
    for (int t = 0; t < 64; ++t) {
        float hv = n0;
        n0 = n1;
        if (t < 62) n1 = hb[(t + 2) * 16384];
        v += hv;
        float sp = (v >= 1.f) ? 1.f : 0.f;
        v -= sp;
        sp += __shfl_down_sync(m, sp, 1);
        sp += __shfl_down_sync(m, sp, 2);
        sp += __shfl_down_sync(m, sp, 8);
        sp += __shfl_down_sync(m, sp, 16);
        if (yin == 0 && (x8 & 3) == 0) ob[t * 1024] = sp * 0.0625f;
    }
}

// ---------------------------------------------------------------------------
// K4: conv7 (4->8ch) on 16x16 — R5 winner: thread = 4 y-rows x 8 couts
// (4 f32x2 cout-pairs), 64-thread group per t, 2 t per 128-thread block.
// Grid (tp 32, n 8) = 256 blocks. Per (cin,dx): 10 LDS.32 + bcast LDS.128
// feed 112 FMA2.
// ---------------------------------------------------------------------------
__global__ __launch_bounds__(128) void k_conv2mm(const float* __restrict__ w1) {
    int tp = blockIdx.x, n = blockIdx.y;
    int tid = threadIdx.x;
    int sub = tid >> 6;                     // which t of the pair
    int lt = tid & 63;
    int x = lt & 15, q = lt >> 4;           // q: y-quad (rows q*4..q*4+3)
    int t = tp * 2 + sub;

    __shared__ float si[2][1936];           // [sub][cin 4][22][22]
    __shared__ ulonglong2 swq[196][2];      // per tap: {(w0,w1),(w2,w3)},{(w4,w5),(w6,w7)}

    for (int e = tid; e < 196; e += 128) {
        int cin = e / 49, j = e - cin * 49;
        float w[8];
#pragma unroll
        for (int co = 0; co < 8; ++co) w[co] = w1[(co * 4 + cin) * 49 + j];
        swq[e][0] = make_ulonglong2(pack2(w[0], w[1]), pack2(w[2], w[3]));
        swq[e][1] = make_ulonglong2(pack2(w[4], w[5]), pack2(w[6], w[7]));
    }

    const float* pt = g_p1 + n * 65536 + t * 1024;
    for (int e = lt; e < 1936; e += 64) {
        int cin = e / 484, rem = e - cin * 484;
        int r = rem / 22, col = rem - r * 22;
        int gy = r - 3, gx = col - 3;
        float val = 0.f;
        if ((unsigned)gy < 16u && (unsigned)gx < 16u)
            val = pt[cin * 256 + gy * 16 + gx];
        si[sub][e] = val;
    }
    __syncthreads();

    unsigned long long a[4][4];             // [row r][cout-pair p]
#pragma unroll
    for (int r = 0; r < 4; ++r)
#pragma unroll
        for (int p = 0; p < 4; ++p) a[r][p] = 0ull;

#pragma unroll 1
    for (int dx = 0; dx < 7; ++dx) {
#pragma unroll
        for (int cin = 0; cin < 4; ++cin) {
            const float* colp = &si[sub][cin * 484 + (q * 4) * 22 + (x + dx)];
            unsigned long long vp[10];
#pragma unroll
            for (int r = 0; r < 10; ++r) {
                float vv = colp[r * 22];
                vp[r] = pack2(vv, vv);
            }
#pragma unroll
            for (int dy = 0; dy < 7; ++dy) {
                ulonglong2 wA = swq[cin * 49 + dy * 7 + dx][0];
                ulonglong2 wB = swq[cin * 49 + dy * 7 + dx][1];
#pragma unroll
                for (int r = 0; r < 4; ++r) {
                    a[r][0] = fma2(vp[dy + r], wA.x, a[r][0]);
                    a[r][1] = fma2(vp[dy + r], wA.y, a[r][1]);
                    a[r][2] = fma2(vp[dy + r], wB.x, a[r][2]);
                    a[r][3] = fma2(vp[dy + r], wB.y, a[r][3]);
                }
            }
        }
    }

    float* hb = g_h2 + (long long)(n * 64 + t) * 2048;
#pragma unroll
    for (int r = 0; r < 4; ++r) {
        int yo = (q * 4 + r) * 16 + x;
#pragma unroll
        for (int p = 0; p < 4; ++p) {
            float2 f = unpack2(a[r][p]);
            hb[(2 * p) * 256 + yo]     = f.x;
            hb[(2 * p + 1) * 256 + yo] = f.y;
        }
    }
}

// ---------------------------------------------------------------------------
// K5: IAF scan layer 2 + avgpool4 -> g_p2 (n,t,128). 2-deep prefetch.
// ---------------------------------------------------------------------------
__global__ __launch_bounds__(256) void k_iaf2() {
    int co = blockIdx.x, n = blockIdx.y;
    int tid = threadIdx.x;
    int w = tid >> 5, lane = tid & 31;
    int yin = lane >> 3, x8 = lane & 7;
    int y = (w >> 1) * 4 + yin;
    int x = (w & 1) * 8 + x8;
    int g = (y >> 2) * 4 + (x >> 2);

    const float* hb = g_h2 + (long long)(n * 64) * 2048 + co * 256 + y * 16 + x;
    float* ob = g_p2 + (n * 64) * 128 + co * 16 + g;
    const unsigned m = 0xffffffffu;

    float v = 0.f;
    float n0 = hb[0];
    float n1 = hb[2048];
    for (int t = 0; t < 64; ++t) {
        float hv = n0;
        n0 = n1;
        if (t < 62) n1 = hb[(t + 2) * 2048];
        v += hv;
        float sp = (v >= 1.f) ? 1.f : 0.f;
        v -= sp;
        sp += __shfl_down_sync(m, sp, 1);
        sp += __shfl_down_sync(m, sp, 2);
        sp += __shfl_down_sync(m, sp, 8);
        sp += __shfl_down_sync(m, sp, 16);
        if (yin == 0 && (x8 & 3) == 0) ob[t * 128] = sp * 0.0625f;
    }
}

// ---------------------------------------------------------------------------
// K6: out[n][cls][t] = sum_f feat[n][t][f] * wl[cls][f]   -> (8,2,64)
// ---------------------------------------------------------------------------
__global__ __launch_bounds__(128) void k_fc(const float* __restrict__ wl,
                                            float* __restrict__ out) {
    int b = blockIdx.x;          // n*64 + t
    int tid = threadIdx.x;
    float v = g_p2[b * 128 + tid];
    float c0 = v * wl[tid];
    float c1 = v * wl[128 + tid];
    const unsigned m = 0xffffffffu;
#pragma unroll
    for (int o = 16; o; o >>= 1) {
        c0 += __shfl_down_sync(m, c0, o);
        c1 += __shfl_down_sync(m, c1, o);
    }
    __shared__ float r0[4], r1[4];
    if ((tid & 31) == 0) { r0[tid >> 5] = c0; r1[tid >> 5] = c1; }
    __syncthreads();
    if (tid == 0) {
        int n = b >> 6, t = b & 63;
        out[n * 128 + t]      = (r0[0] + r0[1]) + (r0[2] + r0[3]);
        out[n * 128 + 64 + t] = (r1[0] + r1[1]) + (r1[2] + r1[3]);
    }
}

// ---------------------------------------------------------------------------
extern "C" void kernel_launch(void* const* d_in, const int* in_sizes, int n_in,
                              void* d_out, int out_size) {
    const float *inp = nullptr, *w0 = nullptr, *w1 = nullptr, *wl = nullptr;
    for (int i = 0; i < n_in; ++i) {
        switch (in_sizes[i]) {
            case 67108864: inp = (const float*)d_in[i]; break;  // (8,2,256,256,64)
            case 392:      w0  = (const float*)d_in[i]; break;  // (4,2,7,7)
            case 1568:     w1  = (const float*)d_in[i]; break;  // (8,4,7,7)
            case 256:      wl  = (const float*)d_in[i]; break;  // (2,128)
        }
    }
    if (!inp) inp = (const float*)d_in[0];
    if (!w0)  w0  = (const float*)d_in[1];
    if (!w1)  w1  = (const float*)d_in[2];
    if (!wl)  wl  = (const float*)d_in[3];

    k_pool   <<<dim3(64, 2, 8),  256>>>(inp);
    k_conv1mm<<<dim3(8, 32, 8),  256>>>(w0);
    k_iaf1   <<<dim3(16, 4, 8),  256>>>();
    k_conv2mm<<<dim3(32, 8),     128>>>(w1);
    k_iaf2   <<<dim3(8, 8),      256>>>();
    k_fc     <<<512,             128>>>(wl, (float*)d_out);
}